// round 10
// baseline (speedup 1.0000x reference)
#include <cuda_runtime.h>

#define BB 4096
#define PP 128
#define GG 128
#define NB_PER_CTA 4
#define GRID (BB / NB_PER_CTA)   // 1024

#define SCX (8000.0f / 79.0f)
#define SCY (8000.0f / 79.0f)
#define SCZ (2000.0f / 19.0f)
#define BX (-4000.0f)
#define BY (-4000.0f)
#define BZ (0.0f)

#define DIST_THRESH_SQ (500.0f * 500.0f)
#define BBOX_THRESH 0.1f
#define EOFF 2.0e8f              // offset keeping e positive for finite inputs
#define KEYMASK (~31)            // drop low 5 float bits, embed q (q < 32)

typedef unsigned long long ull;

// ---- packed f32x2 helpers (sm_103a) ----
__device__ __forceinline__ ull pack2(float lo, float hi) {
    ull r;
    asm("mov.b64 %0, {%1, %2};" : "=l"(r) : "f"(lo), "f"(hi));
    return r;
}
__device__ __forceinline__ void unpack2(ull v, float& lo, float& hi) {
    asm("mov.b64 {%0, %1}, %2;" : "=f"(lo), "=f"(hi) : "l"(v));
}
__device__ __forceinline__ ull fma2(ull a, ull b, ull c) {
    ull r;
    asm("fma.rn.f32x2 %0, %1, %2, %3;" : "=l"(r) : "l"(a), "l"(b), "l"(c));
    return r;
}
// (bits(s) & KEYMASK) | q in a single LOP3
__device__ __forceinline__ int keyfuse(float s, int q) {
    int r;
    asm("lop3.b32 %0, %1, %2, %3, 0xea;"   // (a & b) | c
        : "=r"(r) : "r"(__float_as_int(s)), "n"(KEYMASK), "r"(q));
    return r;
}

// ---- cp.async helpers ----
__device__ __forceinline__ void cpa16(void* s, const void* g) {
    unsigned sa = (unsigned)__cvta_generic_to_shared(s);
    asm volatile("cp.async.ca.shared.global [%0], [%1], 16;" :: "r"(sa), "l"(g));
}
__device__ __forceinline__ void cpa4(void* s, const void* g) {
    unsigned sa = (unsigned)__cvta_generic_to_shared(s);
    asm volatile("cp.async.ca.shared.global [%0], [%1], 4;" :: "r"(sa), "l"(g));
}
#define CPA_COMMIT() asm volatile("cp.async.commit_group;" ::: "memory")
#define CPA_WAIT1()  asm volatile("cp.async.wait_group 1;" ::: "memory")

// raw per-batch staging buffer (all 16B-aligned segments)
struct __align__(16) RawBuf {
    float roots[GG * 3];   // 1536 B
    float bbox [GG * 2];   // 1024 B
    int   tidx [PP * 3];   // 1536 B
    float conf [PP];       //  512 B
    float match[PP * 2];   // 1024 B
    int   np;              //    4 B
    int   pad[3];
};

__global__ __launch_bounds__(PP, 8)
void proposal_layer_kernel(const int*   __restrict__ topk_index,      // [B,P,3]
                           const float* __restrict__ topk_confs,      // [B,P]
                           const float* __restrict__ match_bbox_preds,// [B,P,2]
                           const float* __restrict__ roots_3d,        // [B,G,3]
                           const float* __restrict__ gt_bbox,         // [B,G,2]
                           const int*   __restrict__ num_person,      // [B]
                           float*       __restrict__ out)             // [B,P,7]
{
    const int t = threadIdx.x;  // 0..127

    __shared__ RawBuf raw[2];
    __shared__ __align__(16) float s_nx[GG];
    __shared__ __align__(16) float s_ny[GG];
    __shared__ __align__(16) float s_nz[GG];
    __shared__ __align__(16) float s_h [GG];
    __shared__ float2 s_bbox[GG];
    __shared__ float  s_out[PP * 7];

    // issue one batch's prefetch into buf
    auto prefetch = [&](RawBuf* buf, int b) {
        if (t < 96) cpa16(&buf->roots[t * 4], roots_3d         + (size_t)b * (GG * 3) + t * 4);
        if (t < 64) cpa16(&buf->bbox [t * 4], gt_bbox          + (size_t)b * (GG * 2) + t * 4);
        if (t < 96) cpa16(&buf->tidx [t * 4], topk_index       + (size_t)b * (PP * 3) + t * 4);
        if (t < 32) cpa16(&buf->conf [t * 4], topk_confs       + (size_t)b * PP       + t * 4);
        if (t < 64) cpa16(&buf->match[t * 4], match_bbox_preds + (size_t)b * (PP * 2) + t * 4);
        if (t == 0) cpa4 (&buf->np, num_person + b);
    };

    // prime the pipeline: batches i=0 and i=1
    prefetch(&raw[0], blockIdx.x);            CPA_COMMIT();
    prefetch(&raw[1], blockIdx.x + GRID);     CPA_COMMIT();

    for (int i = 0; i < NB_PER_CTA; ++i) {
        const int b = blockIdx.x + i * GRID;
        RawBuf* rb = &raw[i & 1];

        CPA_WAIT1();              // batch i's data resident (only i+1 may be pending)
        __syncthreads();

        // ---- convert raw -> SoA (+ per-proposal regs) ----
        const int n = rb->np;
        {
            float rx = rb->roots[3 * t], ry = rb->roots[3 * t + 1], rz = rb->roots[3 * t + 2];
            s_nx[t] = -rx;
            s_ny[t] = -ry;
            s_nz[t] = -rz;
            float hv = __fmaf_rn(0.5f, __fmaf_rn(rz, rz, __fmaf_rn(ry, ry, rx * rx)), EOFF);
            s_h[t]  = (t < n) ? hv : __int_as_float(0x7F800000);
            s_bbox[t] = make_float2(rb->bbox[2 * t], rb->bbox[2 * t + 1]);
        }
        const float cx = (float)rb->tidx[3 * t]     * SCX + BX;
        const float cy = (float)rb->tidx[3 * t + 1] * SCY + BY;
        const float cz = (float)rb->tidx[3 * t + 2] * SCZ + BZ;
        const float conf = rb->conf[t];
        const float pb0  = rb->match[2 * t];
        const float pb1  = rb->match[2 * t + 1];
        __syncthreads();          // SoA visible; raw[i&1] fully consumed

        // ---- prefetch batch i+2 into the freed buffer (always commit) ----
        if (i + 2 < NB_PER_CTA) prefetch(rb, b + 2 * GRID);
        CPA_COMMIT();

        // ---- scan: 4 int-key chains over INF-padded chunks ----
        const ull cxx = pack2(cx, cx);
        const ull cyy = pack2(cy, cy);
        const ull czz = pack2(cz, cz);

        const ulonglong2* px = (const ulonglong2*)s_nx;
        const ulonglong2* py = (const ulonglong2*)s_ny;
        const ulonglong2* pz = (const ulonglong2*)s_nz;
        const ulonglong2* ph = (const ulonglong2*)s_h;

        int bk0 = 0x7FFFFFFF, bk1 = 0x7FFFFFFF, bk2 = 0x7FFFFFFF, bk3 = 0x7FFFFFFF;
        const int nbc = (n + 3) >> 2;
        #pragma unroll 2
        for (int q = 0; q < nbc; ++q) {
            ulonglong2 X = px[q];
            ulonglong2 Y = py[q];
            ulonglong2 Z = pz[q];
            ulonglong2 H = ph[q];

            ull eA = fma2(cxx, X.x, fma2(cyy, Y.x, fma2(czz, Z.x, H.x)));
            ull eB = fma2(cxx, X.y, fma2(cyy, Y.y, fma2(czz, Z.y, H.y)));
            float s0, s1, s2, s3;
            unpack2(eA, s0, s1);
            unpack2(eB, s2, s3);

            bk0 = min(bk0, keyfuse(s0, q));
            bk1 = min(bk1, keyfuse(s1, q));
            bk2 = min(bk2, keyfuse(s2, q));
            bk3 = min(bk3, keyfuse(s3, q));
        }

        // merge chains (masked value, strict <; residue order = g order)
        int best_mv = bk0 & KEYMASK;
        int bi = ((bk0 & 31) << 2);
        { int mv = bk1 & KEYMASK; if (mv < best_mv) { best_mv = mv; bi = ((bk1 & 31) << 2) + 1; } }
        { int mv = bk2 & KEYMASK; if (mv < best_mv) { best_mv = mv; bi = ((bk2 & 31) << 2) + 2; } }
        { int mv = bk3 & KEYMASK; if (mv < best_mv) { best_mv = mv; bi = ((bk3 & 31) << 2) + 3; } }

        // exact threshold recheck (fp32, independent of key masking)
        const float cc = __fmaf_rn(cz, cz, __fmaf_rn(cy, cy, cx * cx));
        const float e_best = __fmaf_rn(cx, s_nx[bi],
                            __fmaf_rn(cy, s_ny[bi],
                            __fmaf_rn(cz, s_nz[bi], s_h[bi])));
        const float thresh_e = __fmaf_rn(-0.5f, cc, 0.5f * DIST_THRESH_SQ + EOFF);
        const bool matched = !(e_best > thresh_e);
        const float p2g = matched ? (float)bi : -1.0f;

        float2 mb = s_bbox[bi];
        bool ow = matched && ((pb0 < mb.x - BBOX_THRESH) || (pb1 < mb.y - BBOX_THRESH));
        const float o5 = ow ? mb.x : pb0;
        const float o6 = ow ? mb.y : pb1;

        // ---- stage [P,7] (stride 7 -> conflict-free), coalesced float4 store ----
        float* so = s_out + t * 7;
        so[0] = cx; so[1] = cy; so[2] = cz;
        so[3] = p2g; so[4] = conf;
        so[5] = o5;  so[6] = o6;
        __syncthreads();

        const float4* src = (const float4*)s_out;
        float4* dst = (float4*)(out + (size_t)b * (PP * 7));
        #pragma unroll
        for (int j = t; j < 224; j += PP)   // 896 floats = 224 float4
            dst[j] = src[j];
        // top-of-loop __syncthreads protects s_out / SoA reuse
    }
}

extern "C" void kernel_launch(void* const* d_in, const int* in_sizes, int n_in,
                              void* d_out, int out_size)
{
    const int*   topk_index       = (const int*)  d_in[0];
    const float* topk_confs       = (const float*)d_in[1];
    const float* match_bbox_preds = (const float*)d_in[2];
    const float* roots_3d         = (const float*)d_in[3];
    const float* gt_bbox          = (const float*)d_in[4];
    const int*   num_person       = (const int*)  d_in[5];
    float* out = (float*)d_out;

    proposal_layer_kernel<<<GRID, PP>>>(topk_index, topk_confs, match_bbox_preds,
                                        roots_3d, gt_bbox, num_person, out);
}